// round 7
// baseline (speedup 1.0000x reference)
#include <cuda_runtime.h>
#include <cuda_bf16.h>
#include <cstdint>

// Problem constants
#define BATCH 4
#define SEQ   1024
#define HID   2048
#define NHEAD 16
#define NKV   2
#define HD    128
#define TOK   (BATCH*SEQ)          // 4096
#define KVDIM (NKV*HD)             // 256
#define OUT_ELEMS ((size_t)TOK*HID)        // 8388608
#define BUF_ELEMS ((size_t)2*TOK*2*NKV*HD) // 4194304

// Scratch (device globals — no allocation allowed)
__device__ float g_Q[TOK*HID];
__device__ float g_K[TOK*KVDIM];
__device__ float g_V[TOK*KVDIM];
__device__ float g_A[TOK*HID];

// ---------------------------------------------------------------------------
// tf32 helpers
// ---------------------------------------------------------------------------
__device__ __forceinline__ void split_tf32(float x, uint32_t& hi, uint32_t& lo) {
    uint32_t xb = __float_as_uint(x);
    uint32_t hb = xb & 0xffffe000u;
    hi = hb;
    lo = __float_as_uint(x - __uint_as_float(hb));
}

__device__ __forceinline__ void mma_tf32(float c[4],
    uint32_t a0, uint32_t a1, uint32_t a2, uint32_t a3,
    uint32_t b0, uint32_t b1)
{
    asm volatile(
        "mma.sync.aligned.m16n8k8.row.col.f32.tf32.tf32.f32 "
        "{%0,%1,%2,%3}, {%4,%5,%6,%7}, {%8,%9}, {%0,%1,%2,%3};"
        : "+f"(c[0]), "+f"(c[1]), "+f"(c[2]), "+f"(c[3])
        : "r"(a0), "r"(a1), "r"(a2), "r"(a3), "r"(b0), "r"(b1));
}

// ---------------------------------------------------------------------------
// GEMM-NT via tf32 MMA, 3-pass big/small split (unchanged from R4).
// ---------------------------------------------------------------------------
#define KT 16
#define SST 20

__global__ __launch_bounds__(256) void gemm_tf32_kernel(
    const float* __restrict__ A, const float* __restrict__ B,
    const float* __restrict__ bias, float* __restrict__ C,
    int N, int K)
{
    __shared__ float As[128*SST];
    __shared__ float Bs[128*SST];

    const int tid  = threadIdx.x;
    const int lane = tid & 31;
    const int wid  = tid >> 5;
    const int g    = lane >> 2;
    const int t4   = lane & 3;
    const int wm   = wid >> 2;
    const int wn   = wid & 3;

    const int m0 = blockIdx.y * 128;
    const int n0 = blockIdx.x * 128;

    const int lrow = tid >> 1;
    const int lkq  = (tid & 1) * 8;
    const float* Ag = A + (size_t)(m0 + lrow) * K + lkq;
    const float* Bg = B + (size_t)(n0 + lrow) * K + lkq;

    float acc[16][4];
#pragma unroll
    for (int i = 0; i < 16; i++)
#pragma unroll
        for (int j = 0; j < 4; j++) acc[i][j] = 0.f;

    float4 pa0 = *(const float4*)(Ag);
    float4 pa1 = *(const float4*)(Ag + 4);
    float4 pb0 = *(const float4*)(Bg);
    float4 pb1 = *(const float4*)(Bg + 4);

    for (int k0 = 0; k0 < K; k0 += KT) {
        *(float4*)&As[lrow*SST + lkq]     = pa0;
        *(float4*)&As[lrow*SST + lkq + 4] = pa1;
        *(float4*)&Bs[lrow*SST + lkq]     = pb0;
        *(float4*)&Bs[lrow*SST + lkq + 4] = pb1;
        __syncthreads();

        if (k0 + KT < K) {
            Ag += KT; Bg += KT;
            pa0 = *(const float4*)(Ag);
            pa1 = *(const float4*)(Ag + 4);
            pb0 = *(const float4*)(Bg);
            pb1 = *(const float4*)(Bg + 4);
        }

#pragma unroll
        for (int ks = 0; ks < KT; ks += 8) {
            uint32_t ah[4][4], al[4][4];
#pragma unroll
            for (int mt = 0; mt < 4; mt++) {
                int r = wm*64 + mt*16;
                float x0 = As[(r + g    )*SST + ks + t4];
                float x1 = As[(r + g + 8)*SST + ks + t4];
                float x2 = As[(r + g    )*SST + ks + t4 + 4];
                float x3 = As[(r + g + 8)*SST + ks + t4 + 4];
                split_tf32(x0, ah[mt][0], al[mt][0]);
                split_tf32(x1, ah[mt][1], al[mt][1]);
                split_tf32(x2, ah[mt][2], al[mt][2]);
                split_tf32(x3, ah[mt][3], al[mt][3]);
            }
#pragma unroll
            for (int nt = 0; nt < 4; nt++) {
                int cb = wn*32 + nt*8 + g;
                float y0 = Bs[cb*SST + ks + t4];
                float y1 = Bs[cb*SST + ks + t4 + 4];
                uint32_t bh0, bl0, bh1, bl1;
                split_tf32(y0, bh0, bl0);
                split_tf32(y1, bh1, bl1);
#pragma unroll
                for (int mt = 0; mt < 4; mt++) {
                    float* c = acc[mt*4 + nt];
                    mma_tf32(c, ah[mt][0], ah[mt][1], ah[mt][2], ah[mt][3], bh0, bh1);
                    mma_tf32(c, ah[mt][0], ah[mt][1], ah[mt][2], ah[mt][3], bl0, bl1);
                    mma_tf32(c, al[mt][0], al[mt][1], al[mt][2], al[mt][3], bh0, bh1);
                }
            }
        }
        __syncthreads();
    }

#pragma unroll
    for (int mt = 0; mt < 4; mt++) {
#pragma unroll
        for (int nt = 0; nt < 4; nt++) {
            const float* c = acc[mt*4 + nt];
            int row0 = m0 + wm*64 + mt*16 + g;
            int col  = n0 + wn*32 + nt*8 + 2*t4;
            float b0 = bias ? bias[col]     : 0.f;
            float b1 = bias ? bias[col + 1] : 0.f;
            float2 v0 = make_float2(c[0] + b0, c[1] + b1);
            float2 v1 = make_float2(c[2] + b0, c[3] + b1);
            *(float2*)(C + (size_t)row0 * N + col)       = v0;
            *(float2*)(C + (size_t)(row0 + 8) * N + col) = v1;
        }
    }
}

// ---------------------------------------------------------------------------
// RoPE in place on Q and K.
// ---------------------------------------------------------------------------
__global__ void rope_kernel(float* __restrict__ Q, float* __restrict__ K,
                            const float* __restrict__ cosb,
                            const float* __restrict__ sinb)
{
    int t  = blockIdx.x;
    int hy = blockIdx.y;
    int i  = threadIdx.x;
    int s  = t & (SEQ - 1);
    float c  = cosb[s*HD + i];
    float si = sinb[s*HD + i];
    float* p = (hy < NHEAD) ? (Q + (size_t)t*HID + hy*HD)
                            : (K + (size_t)t*KVDIM + (hy - NHEAD)*HD);
    float x1 = p[i], x2 = p[i + 64];
    p[i]      = x1 * c - x2 * si;
    p[i + 64] = x2 * c + x1 * si;
}

// ---------------------------------------------------------------------------
// Scatter K/V into output kv buffer (dtype-sniffing select_index).
// ---------------------------------------------------------------------------
__global__ void scatter_kernel(const float* __restrict__ K,
                               const float* __restrict__ V,
                               const void* __restrict__ idx,
                               float* __restrict__ buf)
{
    int t = blockIdx.x;
    int d = threadIdx.x;
    const long long* i64 = (const long long*)idx;
    const int*       i32 = (const int*)idx;
    bool is64 = ((unsigned long long)i64[1]) < (unsigned long long)(2*TOK);
    long long row = is64 ? i64[t] : (long long)i32[t];
    if (row < 0 || row >= (long long)(2*TOK)) return;
    size_t base = (size_t)row * 4 * HD;
    buf[base + 0*HD + d] = K[(size_t)t*KVDIM + d];
    buf[base + 1*HD + d] = K[(size_t)t*KVDIM + HD + d];
    buf[base + 2*HD + d] = V[(size_t)t*KVDIM + d];
    buf[base + 3*HD + d] = V[(size_t)t*KVDIM + HD + d];
}

// ---------------------------------------------------------------------------
// Tensor-core flash attention, causal, GQA 8:1.
// BM=128 q-rows x BN=64 keys, 8 warps (warp w owns rows w*16..w*16+15),
// tf32 m16n8k8 MMA + 3-pass split; warp-local online softmax.
// ---------------------------------------------------------------------------
#define ABM 128
#define ABN 64
#define SQ_ST 132   // (4g+t4) conflict-free frag loads
#define SK_ST 132
#define SP_ST 68
#define ATTN_SMEM ((ABM*SQ_ST + 2*ABN*SK_ST + ABM*SP_ST) * sizeof(float))

__global__ __launch_bounds__(256, 1) void attn_mma_kernel(
    const float* __restrict__ Q, const float* __restrict__ K,
    const float* __restrict__ V, float* __restrict__ Aout)
{
    extern __shared__ float sm[];
    float* sq = sm;                       // 128 x 132
    float* sk = sq + ABM*SQ_ST;           // 64 x 132
    float* sv = sk + ABN*SK_ST;           // 64 x 132
    float* sp = sv + ABN*SK_ST;           // 128 x 68

    const int bh  = blockIdx.y;
    const int b   = bh / NHEAD;
    const int h   = bh % NHEAD;
    const int kvh = h / (NHEAD / NKV);
    const int qt  = blockIdx.x;
    const int tid = threadIdx.x;
    const int lane = tid & 31;
    const int wid  = tid >> 5;
    const int g    = lane >> 2;
    const int t4   = lane & 3;
    const float scale = 0.08838834764831845f;

    // load Q tile (128 x 128)
    const float* Qg = Q + (size_t)(b*SEQ + qt*ABM) * HID + h*HD;
    for (int i = tid; i < ABM*32; i += 256) {
        int r = i >> 5, c = i & 31;
        ((float4*)(sq + r*SQ_ST))[c] = ((const float4*)(Qg + (size_t)r*HID))[c];
    }

    float o[16][4];
#pragma unroll
    for (int i = 0; i < 16; i++)
#pragma unroll
        for (int j = 0; j < 4; j++) o[i][j] = 0.f;
    float mrow[2] = {-1e30f, -1e30f};
    float lrow[2] = {0.f, 0.f};

    const int qrow_base = qt*ABM + wid*16;
    const int nkt = 2*qt + 2;

    for (int kt = 0; kt < nkt; kt++) {
        __syncthreads();
        const float* Kg = K + (size_t)(b*SEQ + kt*ABN) * KVDIM + kvh*HD;
        const float* Vg = V + (size_t)(b*SEQ + kt*ABN) * KVDIM + kvh*HD;
        for (int i = tid; i < ABN*32; i += 256) {
            int r = i >> 5, c = i & 31;
            ((float4*)(sk + r*SK_ST))[c] = ((const float4*)(Kg + (size_t)r*KVDIM))[c];
            ((float4*)(sv + r*SK_ST))[c] = ((const float4*)(Vg + (size_t)r*KVDIM))[c];
        }
        __syncthreads();

        const int kcol_base = kt*ABN;
        // warp fully above the diagonal -> nothing to do this block
        if (kcol_base > qrow_base + 15) continue;

        // ---- S = Q K^T (warp stripe: 16 x 64) ----
        float sacc[8][4];
#pragma unroll
        for (int i = 0; i < 8; i++)
#pragma unroll
            for (int j = 0; j < 4; j++) sacc[i][j] = 0.f;

#pragma unroll
        for (int k8 = 0; k8 < HD/8; k8++) {
            uint32_t ah[4], al[4];
            {
                int rb = (wid*16 + g)*SQ_ST + k8*8;
                float x0 = sq[rb + t4];
                float x1 = sq[rb + 8*SQ_ST + t4];
                float x2 = sq[rb + t4 + 4];
                float x3 = sq[rb + 8*SQ_ST + t4 + 4];
                split_tf32(x0, ah[0], al[0]);
                split_tf32(x1, ah[1], al[1]);
                split_tf32(x2, ah[2], al[2]);
                split_tf32(x3, ah[3], al[3]);
            }
#pragma unroll
            for (int nt = 0; nt < 8; nt++) {
                int kb = (nt*8 + g)*SK_ST + k8*8;
                float y0 = sk[kb + t4];
                float y1 = sk[kb + t4 + 4];
                uint32_t bh0, bl0, bh1, bl1;
                split_tf32(y0, bh0, bl0);
                split_tf32(y1, bh1, bl1);
                float* c = sacc[nt];
                mma_tf32(c, ah[0], ah[1], ah[2], ah[3], bh0, bh1);
                mma_tf32(c, ah[0], ah[1], ah[2], ah[3], bl0, bl1);
                mma_tf32(c, al[0], al[1], al[2], al[3], bh0, bh1);
            }
        }

        // ---- mask + online softmax (warp-local) ----
        const bool need_mask = (kcol_base + ABN - 1) > qrow_base;
        float alpha2[2];
#pragma unroll
        for (int hh = 0; hh < 2; hh++) {
            const int qg = qrow_base + g + 8*hh;
            float mx = -1e30f;
#pragma unroll
            for (int nt = 0; nt < 8; nt++) {
#pragma unroll
                for (int j = 0; j < 2; j++) {
                    float s = sacc[nt][2*hh + j] * scale;
                    if (need_mask) {
                        int kg = kcol_base + nt*8 + 2*t4 + j;
                        if (kg > qg) s = -1e30f;
                    }
                    sacc[nt][2*hh + j] = s;
                    mx = fmaxf(mx, s);
                }
            }
            mx = fmaxf(mx, __shfl_xor_sync(0xffffffffu, mx, 1));
            mx = fmaxf(mx, __shfl_xor_sync(0xffffffffu, mx, 2));
            float mnew = fmaxf(mrow[hh], mx);
            float alpha = __expf(mrow[hh] - mnew);
            float sum = 0.f;
            const int prow = (wid*16 + g + 8*hh)*SP_ST;
#pragma unroll
            for (int nt = 0; nt < 8; nt++) {
                float p0 = __expf(sacc[nt][2*hh]     - mnew);
                float p1 = __expf(sacc[nt][2*hh + 1] - mnew);
                *(float2*)(sp + prow + nt*8 + 2*t4) = make_float2(p0, p1);
                sum += p0 + p1;
            }
            sum += __shfl_xor_sync(0xffffffffu, sum, 1);
            sum += __shfl_xor_sync(0xffffffffu, sum, 2);
            lrow[hh] = lrow[hh]*alpha + sum;
            mrow[hh] = mnew;
            alpha2[hh] = alpha;
        }

        // rescale O accumulators
#pragma unroll
        for (int nt = 0; nt < 16; nt++) {
            o[nt][0] *= alpha2[0]; o[nt][1] *= alpha2[0];
            o[nt][2] *= alpha2[1]; o[nt][3] *= alpha2[1];
        }

        __syncwarp();   // sp region is warp-private; order writes vs frag reads

        // ---- O += P V ----
#pragma unroll
        for (int k8 = 0; k8 < ABN/8; k8++) {
            uint32_t ah[4], al[4];
            {
                int rb = (wid*16 + g)*SP_ST + k8*8;
                float x0 = sp[rb + t4];
                float x1 = sp[rb + 8*SP_ST + t4];
                float x2 = sp[rb + t4 + 4];
                float x3 = sp[rb + 8*SP_ST + t4 + 4];
                split_tf32(x0, ah[0], al[0]);
                split_tf32(x1, ah[1], al[1]);
                split_tf32(x2, ah[2], al[2]);
                split_tf32(x3, ah[3], al[3]);
            }
#pragma unroll
            for (int nt = 0; nt < 16; nt++) {
                float y0 = sv[(k8*8 + t4)*SK_ST + nt*8 + g];
                float y1 = sv[(k8*8 + t4 + 4)*SK_ST + nt*8 + g];
                uint32_t bh0, bl0, bh1, bl1;
                split_tf32(y0, bh0, bl0);
                split_tf32(y1, bh1, bl1);
                float* c = o[nt];
                mma_tf32(c, ah[0], ah[1], ah[2], ah[3], bh0, bh1);
                mma_tf32(c, ah[0], ah[1], ah[2], ah[3], bl0, bl1);
                mma_tf32(c, al[0], al[1], al[2], al[3], bh0, bh1);
            }
        }
    }

    // epilogue
    const float inv0 = 1.f / lrow[0];
    const float inv1 = 1.f / lrow[1];
    const int r0 = qt*ABM + wid*16 + g;
    float* Ag0 = Aout + (size_t)(b*SEQ + r0) * HID + h*HD;
    float* Ag1 = Ag0 + 8*(size_t)HID;
#pragma unroll
    for (int nt = 0; nt < 16; nt++) {
        int col = nt*8 + 2*t4;
        *(float2*)(Ag0 + col) = make_float2(o[nt][0]*inv0, o[nt][1]*inv0);
        *(float2*)(Ag1 + col) = make_float2(o[nt][2]*inv1, o[nt][3]*inv1);
    }
}

// ---------------------------------------------------------------------------
// Launch.
// ---------------------------------------------------------------------------
extern "C" void kernel_launch(void* const* d_in, const int* in_sizes, int n_in,
                              void* d_out, int out_size)
{
    const void* slot[12];
    if (n_in >= 12 && in_sizes[0] == (int)(TOK*(size_t)HID)) {
        for (int i = 0; i < 12; i++) slot[i] = d_in[i];
    } else {
        // alphabetical: cos,k_b,k_w,kv_buffer,o_w,q_b,q_w,select_index,sin,v_b,v_w,x
        slot[8]  = d_in[0];
        slot[4]  = d_in[1];
        slot[3]  = d_in[2];
        slot[10] = d_in[3];
        slot[7]  = d_in[4];
        slot[2]  = d_in[5];
        slot[1]  = d_in[6];
        slot[11] = d_in[7];
        slot[9]  = d_in[8];
        slot[6]  = d_in[9];
        slot[5]  = d_in[10];
        slot[0]  = d_in[11];
    }

    const float* x     = (const float*)slot[0];
    const float* q_w   = (const float*)slot[1];
    const float* q_b   = (const float*)slot[2];
    const float* k_w   = (const float*)slot[3];
    const float* k_b   = (const float*)slot[4];
    const float* v_w   = (const float*)slot[5];
    const float* v_b   = (const float*)slot[6];
    const float* o_w   = (const float*)slot[7];
    const float* cosb  = (const float*)slot[8];
    const float* sinb  = (const float*)slot[9];
    const float* kvbuf = (const float*)slot[10];
    const void*  sel   = slot[11];

    float* out = (float*)d_out;
    bool has_buf = (size_t)out_size >= OUT_ELEMS + BUF_ELEMS;
    float* buf_out = out + ((size_t)out_size - BUF_ELEMS);

    float *Q, *K, *V, *A;
    cudaGetSymbolAddress((void**)&Q, g_Q);
    cudaGetSymbolAddress((void**)&K, g_K);
    cudaGetSymbolAddress((void**)&V, g_V);
    cudaGetSymbolAddress((void**)&A, g_A);

    // QKV projections (tf32 tensor-core)
    gemm_tf32_kernel<<<dim3(HID/128, TOK/128), 256>>>(x, q_w, q_b, Q, HID, HID);
    gemm_tf32_kernel<<<dim3(KVDIM/128, TOK/128), 256>>>(x, k_w, k_b, K, KVDIM, HID);
    gemm_tf32_kernel<<<dim3(KVDIM/128, TOK/128), 256>>>(x, v_w, v_b, V, KVDIM, HID);

    // RoPE on Q and K (in place)
    rope_kernel<<<dim3(TOK, NHEAD + NKV), 64>>>(Q, K, cosb, sinb);

    // KV buffer output
    if (has_buf) {
        cudaMemcpyAsync(buf_out, kvbuf, BUF_ELEMS * sizeof(float),
                        cudaMemcpyDeviceToDevice);
        scatter_kernel<<<TOK, 128>>>(K, V, sel, buf_out);
    }

    // Attention (tensor-core flash)
    cudaFuncSetAttribute(attn_mma_kernel,
                         cudaFuncAttributeMaxDynamicSharedMemorySize,
                         (int)ATTN_SMEM);
    attn_mma_kernel<<<dim3(SEQ/ABM, BATCH*NHEAD), 256, ATTN_SMEM>>>(Q, K, V, A);

    // Output projection
    gemm_tf32_kernel<<<dim3(HID/128, TOK/128), 256>>>(A, o_w, nullptr, out, HID, HID);
}

// round 8
// speedup vs baseline: 1.0013x; 1.0013x over previous
#include <cuda_runtime.h>
#include <cuda_bf16.h>
#include <cstdint>

// Problem constants
#define BATCH 4
#define SEQ   1024
#define HID   2048
#define NHEAD 16
#define NKV   2
#define HD    128
#define TOK   (BATCH*SEQ)          // 4096
#define KVDIM (NKV*HD)             // 256
#define OUT_ELEMS ((size_t)TOK*HID)        // 8388608
#define BUF_ELEMS ((size_t)2*TOK*2*NKV*HD) // 4194304

// Scratch (device globals — no allocation allowed)
__device__ float g_Q[TOK*HID];
__device__ float g_K[TOK*KVDIM];
__device__ float g_V[TOK*KVDIM];
__device__ float g_A[TOK*HID];

// ---------------------------------------------------------------------------
// tf32 helpers
// ---------------------------------------------------------------------------
__device__ __forceinline__ void split_tf32(float x, uint32_t& hi, uint32_t& lo) {
    uint32_t xb = __float_as_uint(x);
    uint32_t hb = xb & 0xffffe000u;
    hi = hb;
    lo = __float_as_uint(x - __uint_as_float(hb));
}

__device__ __forceinline__ void mma_tf32(float c[4],
    uint32_t a0, uint32_t a1, uint32_t a2, uint32_t a3,
    uint32_t b0, uint32_t b1)
{
    asm volatile(
        "mma.sync.aligned.m16n8k8.row.col.f32.tf32.tf32.f32 "
        "{%0,%1,%2,%3}, {%4,%5,%6,%7}, {%8,%9}, {%0,%1,%2,%3};"
        : "+f"(c[0]), "+f"(c[1]), "+f"(c[2]), "+f"(c[3])
        : "r"(a0), "r"(a1), "r"(a2), "r"(a3), "r"(b0), "r"(b1));
}

// ---------------------------------------------------------------------------
// GEMM-NT via tf32 MMA, 3-pass big/small split (unchanged from R4).
// ---------------------------------------------------------------------------
#define KT 16
#define SST 20

__global__ __launch_bounds__(256) void gemm_tf32_kernel(
    const float* __restrict__ A, const float* __restrict__ B,
    const float* __restrict__ bias, float* __restrict__ C,
    int N, int K)
{
    __shared__ float As[128*SST];
    __shared__ float Bs[128*SST];

    const int tid  = threadIdx.x;
    const int lane = tid & 31;
    const int wid  = tid >> 5;
    const int g    = lane >> 2;
    const int t4   = lane & 3;
    const int wm   = wid >> 2;
    const int wn   = wid & 3;

    const int m0 = blockIdx.y * 128;
    const int n0 = blockIdx.x * 128;

    const int lrow = tid >> 1;
    const int lkq  = (tid & 1) * 8;
    const float* Ag = A + (size_t)(m0 + lrow) * K + lkq;
    const float* Bg = B + (size_t)(n0 + lrow) * K + lkq;

    float acc[16][4];
#pragma unroll
    for (int i = 0; i < 16; i++)
#pragma unroll
        for (int j = 0; j < 4; j++) acc[i][j] = 0.f;

    float4 pa0 = *(const float4*)(Ag);
    float4 pa1 = *(const float4*)(Ag + 4);
    float4 pb0 = *(const float4*)(Bg);
    float4 pb1 = *(const float4*)(Bg + 4);

    for (int k0 = 0; k0 < K; k0 += KT) {
        *(float4*)&As[lrow*SST + lkq]     = pa0;
        *(float4*)&As[lrow*SST + lkq + 4] = pa1;
        *(float4*)&Bs[lrow*SST + lkq]     = pb0;
        *(float4*)&Bs[lrow*SST + lkq + 4] = pb1;
        __syncthreads();

        if (k0 + KT < K) {
            Ag += KT; Bg += KT;
            pa0 = *(const float4*)(Ag);
            pa1 = *(const float4*)(Ag + 4);
            pb0 = *(const float4*)(Bg);
            pb1 = *(const float4*)(Bg + 4);
        }

#pragma unroll
        for (int ks = 0; ks < KT; ks += 8) {
            uint32_t ah[4][4], al[4][4];
#pragma unroll
            for (int mt = 0; mt < 4; mt++) {
                int r = wm*64 + mt*16;
                float x0 = As[(r + g    )*SST + ks + t4];
                float x1 = As[(r + g + 8)*SST + ks + t4];
                float x2 = As[(r + g    )*SST + ks + t4 + 4];
                float x3 = As[(r + g + 8)*SST + ks + t4 + 4];
                split_tf32(x0, ah[mt][0], al[mt][0]);
                split_tf32(x1, ah[mt][1], al[mt][1]);
                split_tf32(x2, ah[mt][2], al[mt][2]);
                split_tf32(x3, ah[mt][3], al[mt][3]);
            }
#pragma unroll
            for (int nt = 0; nt < 4; nt++) {
                int cb = wn*32 + nt*8 + g;
                float y0 = Bs[cb*SST + ks + t4];
                float y1 = Bs[cb*SST + ks + t4 + 4];
                uint32_t bh0, bl0, bh1, bl1;
                split_tf32(y0, bh0, bl0);
                split_tf32(y1, bh1, bl1);
#pragma unroll
                for (int mt = 0; mt < 4; mt++) {
                    float* c = acc[mt*4 + nt];
                    mma_tf32(c, ah[mt][0], ah[mt][1], ah[mt][2], ah[mt][3], bh0, bh1);
                    mma_tf32(c, ah[mt][0], ah[mt][1], ah[mt][2], ah[mt][3], bl0, bl1);
                    mma_tf32(c, al[mt][0], al[mt][1], al[mt][2], al[mt][3], bh0, bh1);
                }
            }
        }
        __syncthreads();
    }

#pragma unroll
    for (int mt = 0; mt < 4; mt++) {
#pragma unroll
        for (int nt = 0; nt < 4; nt++) {
            const float* c = acc[mt*4 + nt];
            int row0 = m0 + wm*64 + mt*16 + g;
            int col  = n0 + wn*32 + nt*8 + 2*t4;
            float b0 = bias ? bias[col]     : 0.f;
            float b1 = bias ? bias[col + 1] : 0.f;
            float2 v0 = make_float2(c[0] + b0, c[1] + b1);
            float2 v1 = make_float2(c[2] + b0, c[3] + b1);
            *(float2*)(C + (size_t)row0 * N + col)       = v0;
            *(float2*)(C + (size_t)(row0 + 8) * N + col) = v1;
        }
    }
}

// ---------------------------------------------------------------------------
// RoPE in place on Q and K.
// ---------------------------------------------------------------------------
__global__ void rope_kernel(float* __restrict__ Q, float* __restrict__ K,
                            const float* __restrict__ cosb,
                            const float* __restrict__ sinb)
{
    int t  = blockIdx.x;
    int hy = blockIdx.y;
    int i  = threadIdx.x;
    int s  = t & (SEQ - 1);
    float c  = cosb[s*HD + i];
    float si = sinb[s*HD + i];
    float* p = (hy < NHEAD) ? (Q + (size_t)t*HID + hy*HD)
                            : (K + (size_t)t*KVDIM + (hy - NHEAD)*HD);
    float x1 = p[i], x2 = p[i + 64];
    p[i]      = x1 * c - x2 * si;
    p[i + 64] = x2 * c + x1 * si;
}

// ---------------------------------------------------------------------------
// Scatter K/V into output kv buffer (dtype-sniffing select_index).
// ---------------------------------------------------------------------------
__global__ void scatter_kernel(const float* __restrict__ K,
                               const float* __restrict__ V,
                               const void* __restrict__ idx,
                               float* __restrict__ buf)
{
    int t = blockIdx.x;
    int d = threadIdx.x;
    const long long* i64 = (const long long*)idx;
    const int*       i32 = (const int*)idx;
    bool is64 = ((unsigned long long)i64[1]) < (unsigned long long)(2*TOK);
    long long row = is64 ? i64[t] : (long long)i32[t];
    if (row < 0 || row >= (long long)(2*TOK)) return;
    size_t base = (size_t)row * 4 * HD;
    buf[base + 0*HD + d] = K[(size_t)t*KVDIM + d];
    buf[base + 1*HD + d] = K[(size_t)t*KVDIM + HD + d];
    buf[base + 2*HD + d] = V[(size_t)t*KVDIM + d];
    buf[base + 3*HD + d] = V[(size_t)t*KVDIM + HD + d];
}

// ---------------------------------------------------------------------------
// Tensor-core flash attention, causal, GQA 8:1.
// BM=128 q-rows x BN=64 keys, 8 warps (warp w owns rows w*16..w*16+15),
// tf32 m16n8k8 MMA + 3-pass split; warp-local online softmax.
// ---------------------------------------------------------------------------
#define ABM 128
#define ABN 64
#define SQ_ST 132   // (4g+t4) conflict-free frag loads
#define SK_ST 132
#define SP_ST 68
#define ATTN_SMEM ((ABM*SQ_ST + 2*ABN*SK_ST + ABM*SP_ST) * sizeof(float))

__global__ __launch_bounds__(256, 1) void attn_mma_kernel(
    const float* __restrict__ Q, const float* __restrict__ K,
    const float* __restrict__ V, float* __restrict__ Aout)
{
    extern __shared__ float sm[];
    float* sq = sm;                       // 128 x 132
    float* sk = sq + ABM*SQ_ST;           // 64 x 132
    float* sv = sk + ABN*SK_ST;           // 64 x 132
    float* sp = sv + ABN*SK_ST;           // 128 x 68

    const int bh  = blockIdx.y;
    const int b   = bh / NHEAD;
    const int h   = bh % NHEAD;
    const int kvh = h / (NHEAD / NKV);
    const int qt  = blockIdx.x;
    const int tid = threadIdx.x;
    const int lane = tid & 31;
    const int wid  = tid >> 5;
    const int g    = lane >> 2;
    const int t4   = lane & 3;
    const float scale = 0.08838834764831845f;

    // load Q tile (128 x 128)
    const float* Qg = Q + (size_t)(b*SEQ + qt*ABM) * HID + h*HD;
    for (int i = tid; i < ABM*32; i += 256) {
        int r = i >> 5, c = i & 31;
        ((float4*)(sq + r*SQ_ST))[c] = ((const float4*)(Qg + (size_t)r*HID))[c];
    }

    float o[16][4];
#pragma unroll
    for (int i = 0; i < 16; i++)
#pragma unroll
        for (int j = 0; j < 4; j++) o[i][j] = 0.f;
    float mrow[2] = {-1e30f, -1e30f};
    float lrow[2] = {0.f, 0.f};

    const int qrow_base = qt*ABM + wid*16;
    const int nkt = 2*qt + 2;

    for (int kt = 0; kt < nkt; kt++) {
        __syncthreads();
        const float* Kg = K + (size_t)(b*SEQ + kt*ABN) * KVDIM + kvh*HD;
        const float* Vg = V + (size_t)(b*SEQ + kt*ABN) * KVDIM + kvh*HD;
        for (int i = tid; i < ABN*32; i += 256) {
            int r = i >> 5, c = i & 31;
            ((float4*)(sk + r*SK_ST))[c] = ((const float4*)(Kg + (size_t)r*KVDIM))[c];
            ((float4*)(sv + r*SK_ST))[c] = ((const float4*)(Vg + (size_t)r*KVDIM))[c];
        }
        __syncthreads();

        const int kcol_base = kt*ABN;
        // warp fully above the diagonal -> nothing to do this block
        if (kcol_base > qrow_base + 15) continue;

        // ---- S = Q K^T (warp stripe: 16 x 64) ----
        float sacc[8][4];
#pragma unroll
        for (int i = 0; i < 8; i++)
#pragma unroll
            for (int j = 0; j < 4; j++) sacc[i][j] = 0.f;

#pragma unroll
        for (int k8 = 0; k8 < HD/8; k8++) {
            uint32_t ah[4], al[4];
            {
                int rb = (wid*16 + g)*SQ_ST + k8*8;
                float x0 = sq[rb + t4];
                float x1 = sq[rb + 8*SQ_ST + t4];
                float x2 = sq[rb + t4 + 4];
                float x3 = sq[rb + 8*SQ_ST + t4 + 4];
                split_tf32(x0, ah[0], al[0]);
                split_tf32(x1, ah[1], al[1]);
                split_tf32(x2, ah[2], al[2]);
                split_tf32(x3, ah[3], al[3]);
            }
#pragma unroll
            for (int nt = 0; nt < 8; nt++) {
                int kb = (nt*8 + g)*SK_ST + k8*8;
                float y0 = sk[kb + t4];
                float y1 = sk[kb + t4 + 4];
                uint32_t bh0, bl0, bh1, bl1;
                split_tf32(y0, bh0, bl0);
                split_tf32(y1, bh1, bl1);
                float* c = sacc[nt];
                mma_tf32(c, ah[0], ah[1], ah[2], ah[3], bh0, bh1);
                mma_tf32(c, ah[0], ah[1], ah[2], ah[3], bl0, bl1);
                mma_tf32(c, al[0], al[1], al[2], al[3], bh0, bh1);
            }
        }

        // ---- mask + online softmax (warp-local) ----
        const bool need_mask = (kcol_base + ABN - 1) > qrow_base;
        float alpha2[2];
#pragma unroll
        for (int hh = 0; hh < 2; hh++) {
            const int qg = qrow_base + g + 8*hh;
            float mx = -1e30f;
#pragma unroll
            for (int nt = 0; nt < 8; nt++) {
#pragma unroll
                for (int j = 0; j < 2; j++) {
                    float s = sacc[nt][2*hh + j] * scale;
                    if (need_mask) {
                        int kg = kcol_base + nt*8 + 2*t4 + j;
                        if (kg > qg) s = -1e30f;
                    }
                    sacc[nt][2*hh + j] = s;
                    mx = fmaxf(mx, s);
                }
            }
            mx = fmaxf(mx, __shfl_xor_sync(0xffffffffu, mx, 1));
            mx = fmaxf(mx, __shfl_xor_sync(0xffffffffu, mx, 2));
            float mnew = fmaxf(mrow[hh], mx);
            float alpha = __expf(mrow[hh] - mnew);
            float sum = 0.f;
            const int prow = (wid*16 + g + 8*hh)*SP_ST;
#pragma unroll
            for (int nt = 0; nt < 8; nt++) {
                float p0 = __expf(sacc[nt][2*hh]     - mnew);
                float p1 = __expf(sacc[nt][2*hh + 1] - mnew);
                *(float2*)(sp + prow + nt*8 + 2*t4) = make_float2(p0, p1);
                sum += p0 + p1;
            }
            sum += __shfl_xor_sync(0xffffffffu, sum, 1);
            sum += __shfl_xor_sync(0xffffffffu, sum, 2);
            lrow[hh] = lrow[hh]*alpha + sum;
            mrow[hh] = mnew;
            alpha2[hh] = alpha;
        }

        // rescale O accumulators
#pragma unroll
        for (int nt = 0; nt < 16; nt++) {
            o[nt][0] *= alpha2[0]; o[nt][1] *= alpha2[0];
            o[nt][2] *= alpha2[1]; o[nt][3] *= alpha2[1];
        }

        __syncwarp();   // sp region is warp-private; order writes vs frag reads

        // ---- O += P V ----
#pragma unroll
        for (int k8 = 0; k8 < ABN/8; k8++) {
            uint32_t ah[4], al[4];
            {
                int rb = (wid*16 + g)*SP_ST + k8*8;
                float x0 = sp[rb + t4];
                float x1 = sp[rb + 8*SP_ST + t4];
                float x2 = sp[rb + t4 + 4];
                float x3 = sp[rb + 8*SP_ST + t4 + 4];
                split_tf32(x0, ah[0], al[0]);
                split_tf32(x1, ah[1], al[1]);
                split_tf32(x2, ah[2], al[2]);
                split_tf32(x3, ah[3], al[3]);
            }
#pragma unroll
            for (int nt = 0; nt < 16; nt++) {
                float y0 = sv[(k8*8 + t4)*SK_ST + nt*8 + g];
                float y1 = sv[(k8*8 + t4 + 4)*SK_ST + nt*8 + g];
                uint32_t bh0, bl0, bh1, bl1;
                split_tf32(y0, bh0, bl0);
                split_tf32(y1, bh1, bl1);
                float* c = o[nt];
                mma_tf32(c, ah[0], ah[1], ah[2], ah[3], bh0, bh1);
                mma_tf32(c, ah[0], ah[1], ah[2], ah[3], bl0, bl1);
                mma_tf32(c, al[0], al[1], al[2], al[3], bh0, bh1);
            }
        }
    }

    // epilogue
    const float inv0 = 1.f / lrow[0];
    const float inv1 = 1.f / lrow[1];
    const int r0 = qt*ABM + wid*16 + g;
    float* Ag0 = Aout + (size_t)(b*SEQ + r0) * HID + h*HD;
    float* Ag1 = Ag0 + 8*(size_t)HID;
#pragma unroll
    for (int nt = 0; nt < 16; nt++) {
        int col = nt*8 + 2*t4;
        *(float2*)(Ag0 + col) = make_float2(o[nt][0]*inv0, o[nt][1]*inv0);
        *(float2*)(Ag1 + col) = make_float2(o[nt][2]*inv1, o[nt][3]*inv1);
    }
}

// ---------------------------------------------------------------------------
// Launch.
// ---------------------------------------------------------------------------
extern "C" void kernel_launch(void* const* d_in, const int* in_sizes, int n_in,
                              void* d_out, int out_size)
{
    const void* slot[12];
    if (n_in >= 12 && in_sizes[0] == (int)(TOK*(size_t)HID)) {
        for (int i = 0; i < 12; i++) slot[i] = d_in[i];
    } else {
        // alphabetical: cos,k_b,k_w,kv_buffer,o_w,q_b,q_w,select_index,sin,v_b,v_w,x
        slot[8]  = d_in[0];
        slot[4]  = d_in[1];
        slot[3]  = d_in[2];
        slot[10] = d_in[3];
        slot[7]  = d_in[4];
        slot[2]  = d_in[5];
        slot[1]  = d_in[6];
        slot[11] = d_in[7];
        slot[9]  = d_in[8];
        slot[6]  = d_in[9];
        slot[5]  = d_in[10];
        slot[0]  = d_in[11];
    }

    const float* x     = (const float*)slot[0];
    const float* q_w   = (const float*)slot[1];
    const float* q_b   = (const float*)slot[2];
    const float* k_w   = (const float*)slot[3];
    const float* k_b   = (const float*)slot[4];
    const float* v_w   = (const float*)slot[5];
    const float* v_b   = (const float*)slot[6];
    const float* o_w   = (const float*)slot[7];
    const float* cosb  = (const float*)slot[8];
    const float* sinb  = (const float*)slot[9];
    const float* kvbuf = (const float*)slot[10];
    const void*  sel   = slot[11];

    float* out = (float*)d_out;
    bool has_buf = (size_t)out_size >= OUT_ELEMS + BUF_ELEMS;
    float* buf_out = out + ((size_t)out_size - BUF_ELEMS);

    float *Q, *K, *V, *A;
    cudaGetSymbolAddress((void**)&Q, g_Q);
    cudaGetSymbolAddress((void**)&K, g_K);
    cudaGetSymbolAddress((void**)&V, g_V);
    cudaGetSymbolAddress((void**)&A, g_A);

    // QKV projections (tf32 tensor-core)
    gemm_tf32_kernel<<<dim3(HID/128, TOK/128), 256>>>(x, q_w, q_b, Q, HID, HID);
    gemm_tf32_kernel<<<dim3(KVDIM/128, TOK/128), 256>>>(x, k_w, k_b, K, KVDIM, HID);
    gemm_tf32_kernel<<<dim3(KVDIM/128, TOK/128), 256>>>(x, v_w, v_b, V, KVDIM, HID);

    // RoPE on Q and K (in place)
    rope_kernel<<<dim3(TOK, NHEAD + NKV), 64>>>(Q, K, cosb, sinb);

    // KV buffer output
    if (has_buf) {
        cudaMemcpyAsync(buf_out, kvbuf, BUF_ELEMS * sizeof(float),
                        cudaMemcpyDeviceToDevice);
        scatter_kernel<<<TOK, 128>>>(K, V, sel, buf_out);
    }

    // Attention (tensor-core flash)
    cudaFuncSetAttribute(attn_mma_kernel,
                         cudaFuncAttributeMaxDynamicSharedMemorySize,
                         (int)ATTN_SMEM);
    attn_mma_kernel<<<dim3(SEQ/ABM, BATCH*NHEAD), 256, ATTN_SMEM>>>(Q, K, V, A);

    // Output projection
    gemm_tf32_kernel<<<dim3(HID/128, TOK/128), 256>>>(A, o_w, nullptr, out, HID, HID);
}

// round 9
// speedup vs baseline: 1.0026x; 1.0013x over previous
#include <cuda_runtime.h>
#include <cuda_bf16.h>
#include <cstdint>

// Problem constants
#define BATCH 4
#define SEQ   1024
#define HID   2048
#define NHEAD 16
#define NKV   2
#define HD    128
#define TOK   (BATCH*SEQ)          // 4096
#define KVDIM (NKV*HD)             // 256
#define OUT_ELEMS ((size_t)TOK*HID)        // 8388608
#define BUF_ELEMS ((size_t)2*TOK*2*NKV*HD) // 4194304

// Scratch (device globals — no allocation allowed)
__device__ float g_Q[TOK*HID];
__device__ float g_K[TOK*KVDIM];
__device__ float g_V[TOK*KVDIM];
__device__ float g_A[TOK*HID];

// ---------------------------------------------------------------------------
// tf32 helpers
// ---------------------------------------------------------------------------
__device__ __forceinline__ void split_tf32(float x, uint32_t& hi, uint32_t& lo) {
    uint32_t xb = __float_as_uint(x);
    uint32_t hb = xb & 0xffffe000u;
    hi = hb;
    lo = __float_as_uint(x - __uint_as_float(hb));
}

__device__ __forceinline__ void mma_tf32(float c[4],
    uint32_t a0, uint32_t a1, uint32_t a2, uint32_t a3,
    uint32_t b0, uint32_t b1)
{
    asm volatile(
        "mma.sync.aligned.m16n8k8.row.col.f32.tf32.tf32.f32 "
        "{%0,%1,%2,%3}, {%4,%5,%6,%7}, {%8,%9}, {%0,%1,%2,%3};"
        : "+f"(c[0]), "+f"(c[1]), "+f"(c[2]), "+f"(c[3])
        : "r"(a0), "r"(a1), "r"(a2), "r"(a3), "r"(b0), "r"(b1));
}

// ---------------------------------------------------------------------------
// GEMM-NT via tf32 MMA, 3-pass big/small split (unchanged from R4).
// ---------------------------------------------------------------------------
#define KT 16
#define SST 20

__global__ __launch_bounds__(256) void gemm_tf32_kernel(
    const float* __restrict__ A, const float* __restrict__ B,
    const float* __restrict__ bias, float* __restrict__ C,
    int N, int K)
{
    __shared__ float As[128*SST];
    __shared__ float Bs[128*SST];

    const int tid  = threadIdx.x;
    const int lane = tid & 31;
    const int wid  = tid >> 5;
    const int g    = lane >> 2;
    const int t4   = lane & 3;
    const int wm   = wid >> 2;
    const int wn   = wid & 3;

    const int m0 = blockIdx.y * 128;
    const int n0 = blockIdx.x * 128;

    const int lrow = tid >> 1;
    const int lkq  = (tid & 1) * 8;
    const float* Ag = A + (size_t)(m0 + lrow) * K + lkq;
    const float* Bg = B + (size_t)(n0 + lrow) * K + lkq;

    float acc[16][4];
#pragma unroll
    for (int i = 0; i < 16; i++)
#pragma unroll
        for (int j = 0; j < 4; j++) acc[i][j] = 0.f;

    float4 pa0 = *(const float4*)(Ag);
    float4 pa1 = *(const float4*)(Ag + 4);
    float4 pb0 = *(const float4*)(Bg);
    float4 pb1 = *(const float4*)(Bg + 4);

    for (int k0 = 0; k0 < K; k0 += KT) {
        *(float4*)&As[lrow*SST + lkq]     = pa0;
        *(float4*)&As[lrow*SST + lkq + 4] = pa1;
        *(float4*)&Bs[lrow*SST + lkq]     = pb0;
        *(float4*)&Bs[lrow*SST + lkq + 4] = pb1;
        __syncthreads();

        if (k0 + KT < K) {
            Ag += KT; Bg += KT;
            pa0 = *(const float4*)(Ag);
            pa1 = *(const float4*)(Ag + 4);
            pb0 = *(const float4*)(Bg);
            pb1 = *(const float4*)(Bg + 4);
        }

#pragma unroll
        for (int ks = 0; ks < KT; ks += 8) {
            uint32_t ah[4][4], al[4][4];
#pragma unroll
            for (int mt = 0; mt < 4; mt++) {
                int r = wm*64 + mt*16;
                float x0 = As[(r + g    )*SST + ks + t4];
                float x1 = As[(r + g + 8)*SST + ks + t4];
                float x2 = As[(r + g    )*SST + ks + t4 + 4];
                float x3 = As[(r + g + 8)*SST + ks + t4 + 4];
                split_tf32(x0, ah[mt][0], al[mt][0]);
                split_tf32(x1, ah[mt][1], al[mt][1]);
                split_tf32(x2, ah[mt][2], al[mt][2]);
                split_tf32(x3, ah[mt][3], al[mt][3]);
            }
#pragma unroll
            for (int nt = 0; nt < 4; nt++) {
                int cb = wn*32 + nt*8 + g;
                float y0 = Bs[cb*SST + ks + t4];
                float y1 = Bs[cb*SST + ks + t4 + 4];
                uint32_t bh0, bl0, bh1, bl1;
                split_tf32(y0, bh0, bl0);
                split_tf32(y1, bh1, bl1);
#pragma unroll
                for (int mt = 0; mt < 4; mt++) {
                    float* c = acc[mt*4 + nt];
                    mma_tf32(c, ah[mt][0], ah[mt][1], ah[mt][2], ah[mt][3], bh0, bh1);
                    mma_tf32(c, ah[mt][0], ah[mt][1], ah[mt][2], ah[mt][3], bl0, bl1);
                    mma_tf32(c, al[mt][0], al[mt][1], al[mt][2], al[mt][3], bh0, bh1);
                }
            }
        }
        __syncthreads();
    }

#pragma unroll
    for (int mt = 0; mt < 4; mt++) {
#pragma unroll
        for (int nt = 0; nt < 4; nt++) {
            const float* c = acc[mt*4 + nt];
            int row0 = m0 + wm*64 + mt*16 + g;
            int col  = n0 + wn*32 + nt*8 + 2*t4;
            float b0 = bias ? bias[col]     : 0.f;
            float b1 = bias ? bias[col + 1] : 0.f;
            float2 v0 = make_float2(c[0] + b0, c[1] + b1);
            float2 v1 = make_float2(c[2] + b0, c[3] + b1);
            *(float2*)(C + (size_t)row0 * N + col)       = v0;
            *(float2*)(C + (size_t)(row0 + 8) * N + col) = v1;
        }
    }
}

// ---------------------------------------------------------------------------
// RoPE in place on Q and K.
// ---------------------------------------------------------------------------
__global__ void rope_kernel(float* __restrict__ Q, float* __restrict__ K,
                            const float* __restrict__ cosb,
                            const float* __restrict__ sinb)
{
    int t  = blockIdx.x;
    int hy = blockIdx.y;
    int i  = threadIdx.x;
    int s  = t & (SEQ - 1);
    float c  = cosb[s*HD + i];
    float si = sinb[s*HD + i];
    float* p = (hy < NHEAD) ? (Q + (size_t)t*HID + hy*HD)
                            : (K + (size_t)t*KVDIM + (hy - NHEAD)*HD);
    float x1 = p[i], x2 = p[i + 64];
    p[i]      = x1 * c - x2 * si;
    p[i + 64] = x2 * c + x1 * si;
}

// ---------------------------------------------------------------------------
// Scatter K/V into output kv buffer (dtype-sniffing select_index).
// ---------------------------------------------------------------------------
__global__ void scatter_kernel(const float* __restrict__ K,
                               const float* __restrict__ V,
                               const void* __restrict__ idx,
                               float* __restrict__ buf)
{
    int t = blockIdx.x;
    int d = threadIdx.x;
    const long long* i64 = (const long long*)idx;
    const int*       i32 = (const int*)idx;
    bool is64 = ((unsigned long long)i64[1]) < (unsigned long long)(2*TOK);
    long long row = is64 ? i64[t] : (long long)i32[t];
    if (row < 0 || row >= (long long)(2*TOK)) return;
    size_t base = (size_t)row * 4 * HD;
    buf[base + 0*HD + d] = K[(size_t)t*KVDIM + d];
    buf[base + 1*HD + d] = K[(size_t)t*KVDIM + HD + d];
    buf[base + 2*HD + d] = V[(size_t)t*KVDIM + d];
    buf[base + 3*HD + d] = V[(size_t)t*KVDIM + HD + d];
}

// ---------------------------------------------------------------------------
// Tensor-core flash attention, causal, GQA 8:1.
// BM=128 q-rows x BN=64 keys, 8 warps (warp w owns rows w*16..w*16+15),
// tf32 m16n8k8 MMA + 3-pass split; warp-local online softmax.
// ---------------------------------------------------------------------------
#define ABM 128
#define ABN 64
#define SQ_ST 132   // (4g+t4) conflict-free frag loads
#define SK_ST 132
#define SP_ST 68
#define ATTN_SMEM ((ABM*SQ_ST + 2*ABN*SK_ST + ABM*SP_ST) * sizeof(float))

__global__ __launch_bounds__(256, 1) void attn_mma_kernel(
    const float* __restrict__ Q, const float* __restrict__ K,
    const float* __restrict__ V, float* __restrict__ Aout)
{
    extern __shared__ float sm[];
    float* sq = sm;                       // 128 x 132
    float* sk = sq + ABM*SQ_ST;           // 64 x 132
    float* sv = sk + ABN*SK_ST;           // 64 x 132
    float* sp = sv + ABN*SK_ST;           // 128 x 68

    const int bh  = blockIdx.y;
    const int b   = bh / NHEAD;
    const int h   = bh % NHEAD;
    const int kvh = h / (NHEAD / NKV);
    const int qt  = blockIdx.x;
    const int tid = threadIdx.x;
    const int lane = tid & 31;
    const int wid  = tid >> 5;
    const int g    = lane >> 2;
    const int t4   = lane & 3;
    const float scale = 0.08838834764831845f;

    // load Q tile (128 x 128)
    const float* Qg = Q + (size_t)(b*SEQ + qt*ABM) * HID + h*HD;
    for (int i = tid; i < ABM*32; i += 256) {
        int r = i >> 5, c = i & 31;
        ((float4*)(sq + r*SQ_ST))[c] = ((const float4*)(Qg + (size_t)r*HID))[c];
    }

    float o[16][4];
#pragma unroll
    for (int i = 0; i < 16; i++)
#pragma unroll
        for (int j = 0; j < 4; j++) o[i][j] = 0.f;
    float mrow[2] = {-1e30f, -1e30f};
    float lrow[2] = {0.f, 0.f};

    const int qrow_base = qt*ABM + wid*16;
    const int nkt = 2*qt + 2;

    for (int kt = 0; kt < nkt; kt++) {
        __syncthreads();
        const float* Kg = K + (size_t)(b*SEQ + kt*ABN) * KVDIM + kvh*HD;
        const float* Vg = V + (size_t)(b*SEQ + kt*ABN) * KVDIM + kvh*HD;
        for (int i = tid; i < ABN*32; i += 256) {
            int r = i >> 5, c = i & 31;
            ((float4*)(sk + r*SK_ST))[c] = ((const float4*)(Kg + (size_t)r*KVDIM))[c];
            ((float4*)(sv + r*SK_ST))[c] = ((const float4*)(Vg + (size_t)r*KVDIM))[c];
        }
        __syncthreads();

        const int kcol_base = kt*ABN;
        // warp fully above the diagonal -> nothing to do this block
        if (kcol_base > qrow_base + 15) continue;

        // ---- S = Q K^T (warp stripe: 16 x 64) ----
        float sacc[8][4];
#pragma unroll
        for (int i = 0; i < 8; i++)
#pragma unroll
            for (int j = 0; j < 4; j++) sacc[i][j] = 0.f;

#pragma unroll
        for (int k8 = 0; k8 < HD/8; k8++) {
            uint32_t ah[4], al[4];
            {
                int rb = (wid*16 + g)*SQ_ST + k8*8;
                float x0 = sq[rb + t4];
                float x1 = sq[rb + 8*SQ_ST + t4];
                float x2 = sq[rb + t4 + 4];
                float x3 = sq[rb + 8*SQ_ST + t4 + 4];
                split_tf32(x0, ah[0], al[0]);
                split_tf32(x1, ah[1], al[1]);
                split_tf32(x2, ah[2], al[2]);
                split_tf32(x3, ah[3], al[3]);
            }
#pragma unroll
            for (int nt = 0; nt < 8; nt++) {
                int kb = (nt*8 + g)*SK_ST + k8*8;
                float y0 = sk[kb + t4];
                float y1 = sk[kb + t4 + 4];
                uint32_t bh0, bl0, bh1, bl1;
                split_tf32(y0, bh0, bl0);
                split_tf32(y1, bh1, bl1);
                float* c = sacc[nt];
                mma_tf32(c, ah[0], ah[1], ah[2], ah[3], bh0, bh1);
                mma_tf32(c, ah[0], ah[1], ah[2], ah[3], bl0, bl1);
                mma_tf32(c, al[0], al[1], al[2], al[3], bh0, bh1);
            }
        }

        // ---- mask + online softmax (warp-local) ----
        const bool need_mask = (kcol_base + ABN - 1) > qrow_base;
        float alpha2[2];
#pragma unroll
        for (int hh = 0; hh < 2; hh++) {
            const int qg = qrow_base + g + 8*hh;
            float mx = -1e30f;
#pragma unroll
            for (int nt = 0; nt < 8; nt++) {
#pragma unroll
                for (int j = 0; j < 2; j++) {
                    float s = sacc[nt][2*hh + j] * scale;
                    if (need_mask) {
                        int kg = kcol_base + nt*8 + 2*t4 + j;
                        if (kg > qg) s = -1e30f;
                    }
                    sacc[nt][2*hh + j] = s;
                    mx = fmaxf(mx, s);
                }
            }
            mx = fmaxf(mx, __shfl_xor_sync(0xffffffffu, mx, 1));
            mx = fmaxf(mx, __shfl_xor_sync(0xffffffffu, mx, 2));
            float mnew = fmaxf(mrow[hh], mx);
            float alpha = __expf(mrow[hh] - mnew);
            float sum = 0.f;
            const int prow = (wid*16 + g + 8*hh)*SP_ST;
#pragma unroll
            for (int nt = 0; nt < 8; nt++) {
                float p0 = __expf(sacc[nt][2*hh]     - mnew);
                float p1 = __expf(sacc[nt][2*hh + 1] - mnew);
                *(float2*)(sp + prow + nt*8 + 2*t4) = make_float2(p0, p1);
                sum += p0 + p1;
            }
            sum += __shfl_xor_sync(0xffffffffu, sum, 1);
            sum += __shfl_xor_sync(0xffffffffu, sum, 2);
            lrow[hh] = lrow[hh]*alpha + sum;
            mrow[hh] = mnew;
            alpha2[hh] = alpha;
        }

        // rescale O accumulators
#pragma unroll
        for (int nt = 0; nt < 16; nt++) {
            o[nt][0] *= alpha2[0]; o[nt][1] *= alpha2[0];
            o[nt][2] *= alpha2[1]; o[nt][3] *= alpha2[1];
        }

        __syncwarp();   // sp region is warp-private; order writes vs frag reads

        // ---- O += P V ----
#pragma unroll
        for (int k8 = 0; k8 < ABN/8; k8++) {
            uint32_t ah[4], al[4];
            {
                int rb = (wid*16 + g)*SP_ST + k8*8;
                float x0 = sp[rb + t4];
                float x1 = sp[rb + 8*SP_ST + t4];
                float x2 = sp[rb + t4 + 4];
                float x3 = sp[rb + 8*SP_ST + t4 + 4];
                split_tf32(x0, ah[0], al[0]);
                split_tf32(x1, ah[1], al[1]);
                split_tf32(x2, ah[2], al[2]);
                split_tf32(x3, ah[3], al[3]);
            }
#pragma unroll
            for (int nt = 0; nt < 16; nt++) {
                float y0 = sv[(k8*8 + t4)*SK_ST + nt*8 + g];
                float y1 = sv[(k8*8 + t4 + 4)*SK_ST + nt*8 + g];
                uint32_t bh0, bl0, bh1, bl1;
                split_tf32(y0, bh0, bl0);
                split_tf32(y1, bh1, bl1);
                float* c = o[nt];
                mma_tf32(c, ah[0], ah[1], ah[2], ah[3], bh0, bh1);
                mma_tf32(c, ah[0], ah[1], ah[2], ah[3], bl0, bl1);
                mma_tf32(c, al[0], al[1], al[2], al[3], bh0, bh1);
            }
        }
    }

    // epilogue
    const float inv0 = 1.f / lrow[0];
    const float inv1 = 1.f / lrow[1];
    const int r0 = qt*ABM + wid*16 + g;
    float* Ag0 = Aout + (size_t)(b*SEQ + r0) * HID + h*HD;
    float* Ag1 = Ag0 + 8*(size_t)HID;
#pragma unroll
    for (int nt = 0; nt < 16; nt++) {
        int col = nt*8 + 2*t4;
        *(float2*)(Ag0 + col) = make_float2(o[nt][0]*inv0, o[nt][1]*inv0);
        *(float2*)(Ag1 + col) = make_float2(o[nt][2]*inv1, o[nt][3]*inv1);
    }
}

// ---------------------------------------------------------------------------
// Launch.
// ---------------------------------------------------------------------------
extern "C" void kernel_launch(void* const* d_in, const int* in_sizes, int n_in,
                              void* d_out, int out_size)
{
    const void* slot[12];
    if (n_in >= 12 && in_sizes[0] == (int)(TOK*(size_t)HID)) {
        for (int i = 0; i < 12; i++) slot[i] = d_in[i];
    } else {
        // alphabetical: cos,k_b,k_w,kv_buffer,o_w,q_b,q_w,select_index,sin,v_b,v_w,x
        slot[8]  = d_in[0];
        slot[4]  = d_in[1];
        slot[3]  = d_in[2];
        slot[10] = d_in[3];
        slot[7]  = d_in[4];
        slot[2]  = d_in[5];
        slot[1]  = d_in[6];
        slot[11] = d_in[7];
        slot[9]  = d_in[8];
        slot[6]  = d_in[9];
        slot[5]  = d_in[10];
        slot[0]  = d_in[11];
    }

    const float* x     = (const float*)slot[0];
    const float* q_w   = (const float*)slot[1];
    const float* q_b   = (const float*)slot[2];
    const float* k_w   = (const float*)slot[3];
    const float* k_b   = (const float*)slot[4];
    const float* v_w   = (const float*)slot[5];
    const float* v_b   = (const float*)slot[6];
    const float* o_w   = (const float*)slot[7];
    const float* cosb  = (const float*)slot[8];
    const float* sinb  = (const float*)slot[9];
    const float* kvbuf = (const float*)slot[10];
    const void*  sel   = slot[11];

    float* out = (float*)d_out;
    bool has_buf = (size_t)out_size >= OUT_ELEMS + BUF_ELEMS;
    float* buf_out = out + ((size_t)out_size - BUF_ELEMS);

    float *Q, *K, *V, *A;
    cudaGetSymbolAddress((void**)&Q, g_Q);
    cudaGetSymbolAddress((void**)&K, g_K);
    cudaGetSymbolAddress((void**)&V, g_V);
    cudaGetSymbolAddress((void**)&A, g_A);

    // QKV projections (tf32 tensor-core)
    gemm_tf32_kernel<<<dim3(HID/128, TOK/128), 256>>>(x, q_w, q_b, Q, HID, HID);
    gemm_tf32_kernel<<<dim3(KVDIM/128, TOK/128), 256>>>(x, k_w, k_b, K, KVDIM, HID);
    gemm_tf32_kernel<<<dim3(KVDIM/128, TOK/128), 256>>>(x, v_w, v_b, V, KVDIM, HID);

    // RoPE on Q and K (in place)
    rope_kernel<<<dim3(TOK, NHEAD + NKV), 64>>>(Q, K, cosb, sinb);

    // KV buffer output
    if (has_buf) {
        cudaMemcpyAsync(buf_out, kvbuf, BUF_ELEMS * sizeof(float),
                        cudaMemcpyDeviceToDevice);
        scatter_kernel<<<TOK, 128>>>(K, V, sel, buf_out);
    }

    // Attention (tensor-core flash)
    cudaFuncSetAttribute(attn_mma_kernel,
                         cudaFuncAttributeMaxDynamicSharedMemorySize,
                         (int)ATTN_SMEM);
    attn_mma_kernel<<<dim3(SEQ/ABM, BATCH*NHEAD), 256, ATTN_SMEM>>>(Q, K, V, A);

    // Output projection
    gemm_tf32_kernel<<<dim3(HID/128, TOK/128), 256>>>(A, o_w, nullptr, out, HID, HID);
}

// round 10
// speedup vs baseline: 1.3392x; 1.3358x over previous
#include <cuda_runtime.h>
#include <cuda_bf16.h>
#include <cstdint>

// Problem constants
#define BATCH 4
#define SEQ   1024
#define HID   2048
#define NHEAD 16
#define NKV   2
#define HD    128
#define TOK   (BATCH*SEQ)          // 4096
#define KVDIM (NKV*HD)             // 256
#define OUT_ELEMS ((size_t)TOK*HID)        // 8388608
#define BUF_ELEMS ((size_t)2*TOK*2*NKV*HD) // 4194304

// Scratch (device globals — no allocation allowed)
__device__ float g_Q[TOK*HID];
__device__ float g_K[TOK*KVDIM];
__device__ float g_V[TOK*KVDIM];
__device__ float g_A[TOK*HID];

// ---------------------------------------------------------------------------
// bf16 split helpers: x = hi + lo, both bf16; packed 2 elements per reg.
// hi = rn_bf16(x); lo = rn_bf16(x - hi). Dropped lo*lo term ~2^-16 rel.
// ---------------------------------------------------------------------------
__device__ __forceinline__ void split_bf16(float x0, float x1,
                                           uint32_t& hi, uint32_t& lo)
{
    // pack: lo half = x0, hi half = x1
    asm("cvt.rn.bf16x2.f32 %0, %1, %2;" : "=r"(hi) : "f"(x1), "f"(x0));
    float h0 = __uint_as_float(hi << 16);
    float h1 = __uint_as_float(hi & 0xffff0000u);
    asm("cvt.rn.bf16x2.f32 %0, %1, %2;" : "=r"(lo) : "f"(x1 - h1), "f"(x0 - h0));
}

__device__ __forceinline__ void mma_bf16(float c[4],
    uint32_t a0, uint32_t a1, uint32_t a2, uint32_t a3,
    uint32_t b0, uint32_t b1)
{
    asm volatile(
        "mma.sync.aligned.m16n8k16.row.col.f32.bf16.bf16.f32 "
        "{%0,%1,%2,%3}, {%4,%5,%6,%7}, {%8,%9}, {%0,%1,%2,%3};"
        : "+f"(c[0]), "+f"(c[1]), "+f"(c[2]), "+f"(c[3])
        : "r"(a0), "r"(a1), "r"(a2), "r"(a3), "r"(b0), "r"(b1));
}

// ---------------------------------------------------------------------------
// GEMM-NT via bf16 MMA (3-pass split): C[m,n] = sum_k A[m,k]*B[n,k] (+bias)
// Block 128x128, ktile 16, 8 warps (2x4), warp tile 64x32.
// smem stride 24 floats -> conflict-free LDS.64 fragment loads.
// ---------------------------------------------------------------------------
#define KT 16
#define SST 24

__global__ __launch_bounds__(256) void gemm_bf16_kernel(
    const float* __restrict__ A, const float* __restrict__ B,
    const float* __restrict__ bias, float* __restrict__ C,
    int N, int K)
{
    __shared__ float As[128*SST];
    __shared__ float Bs[128*SST];

    const int tid  = threadIdx.x;
    const int lane = tid & 31;
    const int wid  = tid >> 5;
    const int g    = lane >> 2;
    const int t4   = lane & 3;
    const int wm   = wid >> 2;
    const int wn   = wid & 3;

    const int m0 = blockIdx.y * 128;
    const int n0 = blockIdx.x * 128;

    const int lrow = tid >> 1;
    const int lkq  = (tid & 1) * 8;
    const float* Ag = A + (size_t)(m0 + lrow) * K + lkq;
    const float* Bg = B + (size_t)(n0 + lrow) * K + lkq;

    float acc[16][4];
#pragma unroll
    for (int i = 0; i < 16; i++)
#pragma unroll
        for (int j = 0; j < 4; j++) acc[i][j] = 0.f;

    float4 pa0 = *(const float4*)(Ag);
    float4 pa1 = *(const float4*)(Ag + 4);
    float4 pb0 = *(const float4*)(Bg);
    float4 pb1 = *(const float4*)(Bg + 4);

    for (int k0 = 0; k0 < K; k0 += KT) {
        *(float4*)&As[lrow*SST + lkq]     = pa0;
        *(float4*)&As[lrow*SST + lkq + 4] = pa1;
        *(float4*)&Bs[lrow*SST + lkq]     = pb0;
        *(float4*)&Bs[lrow*SST + lkq + 4] = pb1;
        __syncthreads();

        if (k0 + KT < K) {
            Ag += KT; Bg += KT;
            pa0 = *(const float4*)(Ag);
            pa1 = *(const float4*)(Ag + 4);
            pb0 = *(const float4*)(Bg);
            pb1 = *(const float4*)(Bg + 4);
        }

        // one k16 MMA step covers the whole ktile
        uint32_t ah[4][4], al[4][4];
#pragma unroll
        for (int mt = 0; mt < 4; mt++) {
            int rb  = (wm*64 + mt*16 + g)*SST;
            int rb8 = rb + 8*SST;
            float2 x0 = *(const float2*)&As[rb  + 2*t4];
            float2 x1 = *(const float2*)&As[rb8 + 2*t4];
            float2 x2 = *(const float2*)&As[rb  + 2*t4 + 8];
            float2 x3 = *(const float2*)&As[rb8 + 2*t4 + 8];
            split_bf16(x0.x, x0.y, ah[mt][0], al[mt][0]);
            split_bf16(x1.x, x1.y, ah[mt][1], al[mt][1]);
            split_bf16(x2.x, x2.y, ah[mt][2], al[mt][2]);
            split_bf16(x3.x, x3.y, ah[mt][3], al[mt][3]);
        }
#pragma unroll
        for (int nt = 0; nt < 4; nt++) {
            int cb = (wn*32 + nt*8 + g)*SST;
            float2 y0 = *(const float2*)&Bs[cb + 2*t4];
            float2 y1 = *(const float2*)&Bs[cb + 2*t4 + 8];
            uint32_t bh0, bl0, bh1, bl1;
            split_bf16(y0.x, y0.y, bh0, bl0);
            split_bf16(y1.x, y1.y, bh1, bl1);
#pragma unroll
            for (int mt = 0; mt < 4; mt++) {
                float* c = acc[mt*4 + nt];
                mma_bf16(c, ah[mt][0], ah[mt][1], ah[mt][2], ah[mt][3], bh0, bh1);
                mma_bf16(c, ah[mt][0], ah[mt][1], ah[mt][2], ah[mt][3], bl0, bl1);
                mma_bf16(c, al[mt][0], al[mt][1], al[mt][2], al[mt][3], bh0, bh1);
            }
        }
        __syncthreads();
    }

#pragma unroll
    for (int mt = 0; mt < 4; mt++) {
#pragma unroll
        for (int nt = 0; nt < 4; nt++) {
            const float* c = acc[mt*4 + nt];
            int row0 = m0 + wm*64 + mt*16 + g;
            int col  = n0 + wn*32 + nt*8 + 2*t4;
            float b0 = bias ? bias[col]     : 0.f;
            float b1 = bias ? bias[col + 1] : 0.f;
            float2 v0 = make_float2(c[0] + b0, c[1] + b1);
            float2 v1 = make_float2(c[2] + b0, c[3] + b1);
            *(float2*)(C + (size_t)row0 * N + col)       = v0;
            *(float2*)(C + (size_t)(row0 + 8) * N + col) = v1;
        }
    }
}

// ---------------------------------------------------------------------------
// RoPE in place on Q and K.
// ---------------------------------------------------------------------------
__global__ void rope_kernel(float* __restrict__ Q, float* __restrict__ K,
                            const float* __restrict__ cosb,
                            const float* __restrict__ sinb)
{
    int t  = blockIdx.x;
    int hy = blockIdx.y;
    int i  = threadIdx.x;
    int s  = t & (SEQ - 1);
    float c  = cosb[s*HD + i];
    float si = sinb[s*HD + i];
    float* p = (hy < NHEAD) ? (Q + (size_t)t*HID + hy*HD)
                            : (K + (size_t)t*KVDIM + (hy - NHEAD)*HD);
    float x1 = p[i], x2 = p[i + 64];
    p[i]      = x1 * c - x2 * si;
    p[i + 64] = x2 * c + x1 * si;
}

// ---------------------------------------------------------------------------
// Scatter K/V into output kv buffer (dtype-sniffing select_index).
// ---------------------------------------------------------------------------
__global__ void scatter_kernel(const float* __restrict__ K,
                               const float* __restrict__ V,
                               const void* __restrict__ idx,
                               float* __restrict__ buf)
{
    int t = blockIdx.x;
    int d = threadIdx.x;
    const long long* i64 = (const long long*)idx;
    const int*       i32 = (const int*)idx;
    bool is64 = ((unsigned long long)i64[1]) < (unsigned long long)(2*TOK);
    long long row = is64 ? i64[t] : (long long)i32[t];
    if (row < 0 || row >= (long long)(2*TOK)) return;
    size_t base = (size_t)row * 4 * HD;
    buf[base + 0*HD + d] = K[(size_t)t*KVDIM + d];
    buf[base + 1*HD + d] = K[(size_t)t*KVDIM + HD + d];
    buf[base + 2*HD + d] = V[(size_t)t*KVDIM + d];
    buf[base + 3*HD + d] = V[(size_t)t*KVDIM + HD + d];
}

// ---------------------------------------------------------------------------
// Tensor-core flash attention, causal, GQA 8:1, bf16 3-pass m16n8k16.
// BM=128 q-rows x BN=64 keys, 8 warps; warp-local online softmax.
// ---------------------------------------------------------------------------
#define ABM 128
#define ABN 64
#define SQ_ST 136   // a-frag loads: 68 ≡ 4 (mod 16) -> conflict-free LDS.64
#define SK_ST 136   // b-frag (K, k-major rows indexed by key*g) same condition
#define SV_ST 132   // V read key-major: 8*t4+g distinct mod 32 -> conflict-free
#define SP_ST 72    // 36 ≡ 4 (mod 16)
#define ATTN_SMEM ((ABM*SQ_ST + ABN*SK_ST + ABN*SV_ST + ABM*SP_ST) * sizeof(float))

__global__ __launch_bounds__(256, 1) void attn_mma_kernel(
    const float* __restrict__ Q, const float* __restrict__ K,
    const float* __restrict__ V, float* __restrict__ Aout)
{
    extern __shared__ float sm[];
    float* sq = sm;                       // 128 x 136
    float* sk = sq + ABM*SQ_ST;           // 64 x 136
    float* sv = sk + ABN*SK_ST;           // 64 x 132
    float* sp = sv + ABN*SV_ST;           // 128 x 72

    const int bh  = blockIdx.y;
    const int b   = bh / NHEAD;
    const int h   = bh % NHEAD;
    const int kvh = h / (NHEAD / NKV);
    const int qt  = blockIdx.x;
    const int tid = threadIdx.x;
    const int lane = tid & 31;
    const int wid  = tid >> 5;
    const int g    = lane >> 2;
    const int t4   = lane & 3;
    const float scale = 0.08838834764831845f;

    const float* Qg = Q + (size_t)(b*SEQ + qt*ABM) * HID + h*HD;
    for (int i = tid; i < ABM*32; i += 256) {
        int r = i >> 5, c = i & 31;
        ((float4*)(sq + r*SQ_ST))[c] = ((const float4*)(Qg + (size_t)r*HID))[c];
    }

    float o[16][4];
#pragma unroll
    for (int i = 0; i < 16; i++)
#pragma unroll
        for (int j = 0; j < 4; j++) o[i][j] = 0.f;
    float mrow[2] = {-1e30f, -1e30f};
    float lrow[2] = {0.f, 0.f};

    const int qrow_base = qt*ABM + wid*16;
    const int nkt = 2*qt + 2;

    for (int kt = 0; kt < nkt; kt++) {
        __syncthreads();
        const float* Kg = K + (size_t)(b*SEQ + kt*ABN) * KVDIM + kvh*HD;
        const float* Vg = V + (size_t)(b*SEQ + kt*ABN) * KVDIM + kvh*HD;
        for (int i = tid; i < ABN*32; i += 256) {
            int r = i >> 5, c = i & 31;
            ((float4*)(sk + r*SK_ST))[c] = ((const float4*)(Kg + (size_t)r*KVDIM))[c];
            ((float4*)(sv + r*SV_ST))[c] = ((const float4*)(Vg + (size_t)r*KVDIM))[c];
        }
        __syncthreads();

        const int kcol_base = kt*ABN;
        if (kcol_base > qrow_base + 15) continue;

        // ---- S = Q K^T (warp stripe: 16 x 64), k16 steps over d ----
        float sacc[8][4];
#pragma unroll
        for (int i = 0; i < 8; i++)
#pragma unroll
            for (int j = 0; j < 4; j++) sacc[i][j] = 0.f;

#pragma unroll
        for (int kk = 0; kk < HD/16; kk++) {
            uint32_t ah[4], al[4];
            {
                int rb  = (wid*16 + g)*SQ_ST + kk*16;
                int rb8 = rb + 8*SQ_ST;
                float2 x0 = *(const float2*)&sq[rb  + 2*t4];
                float2 x1 = *(const float2*)&sq[rb8 + 2*t4];
                float2 x2 = *(const float2*)&sq[rb  + 2*t4 + 8];
                float2 x3 = *(const float2*)&sq[rb8 + 2*t4 + 8];
                split_bf16(x0.x, x0.y, ah[0], al[0]);
                split_bf16(x1.x, x1.y, ah[1], al[1]);
                split_bf16(x2.x, x2.y, ah[2], al[2]);
                split_bf16(x3.x, x3.y, ah[3], al[3]);
            }
#pragma unroll
            for (int nt = 0; nt < 8; nt++) {
                int kb = (nt*8 + g)*SK_ST + kk*16;
                float2 y0 = *(const float2*)&sk[kb + 2*t4];
                float2 y1 = *(const float2*)&sk[kb + 2*t4 + 8];
                uint32_t bh0, bl0, bh1, bl1;
                split_bf16(y0.x, y0.y, bh0, bl0);
                split_bf16(y1.x, y1.y, bh1, bl1);
                float* c = sacc[nt];
                mma_bf16(c, ah[0], ah[1], ah[2], ah[3], bh0, bh1);
                mma_bf16(c, ah[0], ah[1], ah[2], ah[3], bl0, bl1);
                mma_bf16(c, al[0], al[1], al[2], al[3], bh0, bh1);
            }
        }

        // ---- mask + online softmax (warp-local) ----
        const bool need_mask = (kcol_base + ABN - 1) > qrow_base;
        float alpha2[2];
#pragma unroll
        for (int hh = 0; hh < 2; hh++) {
            const int qg = qrow_base + g + 8*hh;
            float mx = -1e30f;
#pragma unroll
            for (int nt = 0; nt < 8; nt++) {
#pragma unroll
                for (int j = 0; j < 2; j++) {
                    float s = sacc[nt][2*hh + j] * scale;
                    if (need_mask) {
                        int kg = kcol_base + nt*8 + 2*t4 + j;
                        if (kg > qg) s = -1e30f;
                    }
                    sacc[nt][2*hh + j] = s;
                    mx = fmaxf(mx, s);
                }
            }
            mx = fmaxf(mx, __shfl_xor_sync(0xffffffffu, mx, 1));
            mx = fmaxf(mx, __shfl_xor_sync(0xffffffffu, mx, 2));
            float mnew = fmaxf(mrow[hh], mx);
            float alpha = __expf(mrow[hh] - mnew);
            float sum = 0.f;
            const int prow = (wid*16 + g + 8*hh)*SP_ST;
#pragma unroll
            for (int nt = 0; nt < 8; nt++) {
                float p0 = __expf(sacc[nt][2*hh]     - mnew);
                float p1 = __expf(sacc[nt][2*hh + 1] - mnew);
                *(float2*)(sp + prow + nt*8 + 2*t4) = make_float2(p0, p1);
                sum += p0 + p1;
            }
            sum += __shfl_xor_sync(0xffffffffu, sum, 1);
            sum += __shfl_xor_sync(0xffffffffu, sum, 2);
            lrow[hh] = lrow[hh]*alpha + sum;
            mrow[hh] = mnew;
            alpha2[hh] = alpha;
        }

#pragma unroll
        for (int nt = 0; nt < 16; nt++) {
            o[nt][0] *= alpha2[0]; o[nt][1] *= alpha2[0];
            o[nt][2] *= alpha2[1]; o[nt][3] *= alpha2[1];
        }

        __syncwarp();   // sp is warp-private; order writes vs frag reads

        // ---- O += P V, k16 steps over keys ----
#pragma unroll
        for (int kk = 0; kk < ABN/16; kk++) {
            uint32_t ah[4], al[4];
            {
                int rb  = (wid*16 + g)*SP_ST + kk*16;
                int rb8 = rb + 8*SP_ST;
                float2 x0 = *(const float2*)&sp[rb  + 2*t4];
                float2 x1 = *(const float2*)&sp[rb8 + 2*t4];
                float2 x2 = *(const float2*)&sp[rb  + 2*t4 + 8];
                float2 x3 = *(const float2*)&sp[rb8 + 2*t4 + 8];
                split_bf16(x0.x, x0.y, ah[0], al[0]);
                split_bf16(x1.x, x1.y, ah[1], al[1]);
                split_bf16(x2.x, x2.y, ah[2], al[2]);
                split_bf16(x3.x, x3.y, ah[3], al[3]);
            }
            const int kb = kk*16;
#pragma unroll
            for (int nt = 0; nt < 16; nt++) {
                const int col = nt*8 + g;
                float v00 = sv[(kb + 2*t4    )*SV_ST + col];
                float v01 = sv[(kb + 2*t4 + 1)*SV_ST + col];
                float v10 = sv[(kb + 2*t4 + 8)*SV_ST + col];
                float v11 = sv[(kb + 2*t4 + 9)*SV_ST + col];
                uint32_t bh0, bl0, bh1, bl1;
                split_bf16(v00, v01, bh0, bl0);
                split_bf16(v10, v11, bh1, bl1);
                float* c = o[nt];
                mma_bf16(c, ah[0], ah[1], ah[2], ah[3], bh0, bh1);
                mma_bf16(c, ah[0], ah[1], ah[2], ah[3], bl0, bl1);
                mma_bf16(c, al[0], al[1], al[2], al[3], bh0, bh1);
            }
        }
    }

    // epilogue
    const float inv0 = 1.f / lrow[0];
    const float inv1 = 1.f / lrow[1];
    const int r0 = qt*ABM + wid*16 + g;
    float* Ag0 = Aout + (size_t)(b*SEQ + r0) * HID + h*HD;
    float* Ag1 = Ag0 + 8*(size_t)HID;
#pragma unroll
    for (int nt = 0; nt < 16; nt++) {
        int col = nt*8 + 2*t4;
        *(float2*)(Ag0 + col) = make_float2(o[nt][0]*inv0, o[nt][1]*inv0);
        *(float2*)(Ag1 + col) = make_float2(o[nt][2]*inv1, o[nt][3]*inv1);
    }
}

// ---------------------------------------------------------------------------
// Launch.
// ---------------------------------------------------------------------------
extern "C" void kernel_launch(void* const* d_in, const int* in_sizes, int n_in,
                              void* d_out, int out_size)
{
    const void* slot[12];
    if (n_in >= 12 && in_sizes[0] == (int)(TOK*(size_t)HID)) {
        for (int i = 0; i < 12; i++) slot[i] = d_in[i];
    } else {
        // alphabetical: cos,k_b,k_w,kv_buffer,o_w,q_b,q_w,select_index,sin,v_b,v_w,x
        slot[8]  = d_in[0];
        slot[4]  = d_in[1];
        slot[3]  = d_in[2];
        slot[10] = d_in[3];
        slot[7]  = d_in[4];
        slot[2]  = d_in[5];
        slot[1]  = d_in[6];
        slot[11] = d_in[7];
        slot[9]  = d_in[8];
        slot[6]  = d_in[9];
        slot[5]  = d_in[10];
        slot[0]  = d_in[11];
    }

    const float* x     = (const float*)slot[0];
    const float* q_w   = (const float*)slot[1];
    const float* q_b   = (const float*)slot[2];
    const float* k_w   = (const float*)slot[3];
    const float* k_b   = (const float*)slot[4];
    const float* v_w   = (const float*)slot[5];
    const float* v_b   = (const float*)slot[6];
    const float* o_w   = (const float*)slot[7];
    const float* cosb  = (const float*)slot[8];
    const float* sinb  = (const float*)slot[9];
    const float* kvbuf = (const float*)slot[10];
    const void*  sel   = slot[11];

    float* out = (float*)d_out;
    bool has_buf = (size_t)out_size >= OUT_ELEMS + BUF_ELEMS;
    float* buf_out = out + ((size_t)out_size - BUF_ELEMS);

    float *Q, *K, *V, *A;
    cudaGetSymbolAddress((void**)&Q, g_Q);
    cudaGetSymbolAddress((void**)&K, g_K);
    cudaGetSymbolAddress((void**)&V, g_V);
    cudaGetSymbolAddress((void**)&A, g_A);

    // QKV projections (bf16 tensor-core, 3-pass split)
    gemm_bf16_kernel<<<dim3(HID/128, TOK/128), 256>>>(x, q_w, q_b, Q, HID, HID);
    gemm_bf16_kernel<<<dim3(KVDIM/128, TOK/128), 256>>>(x, k_w, k_b, K, KVDIM, HID);
    gemm_bf16_kernel<<<dim3(KVDIM/128, TOK/128), 256>>>(x, v_w, v_b, V, KVDIM, HID);

    // RoPE on Q and K (in place)
    rope_kernel<<<dim3(TOK, NHEAD + NKV), 64>>>(Q, K, cosb, sinb);

    // KV buffer output
    if (has_buf) {
        cudaMemcpyAsync(buf_out, kvbuf, BUF_ELEMS * sizeof(float),
                        cudaMemcpyDeviceToDevice);
        scatter_kernel<<<TOK, 128>>>(K, V, sel, buf_out);
    }

    // Attention (bf16 tensor-core flash)
    cudaFuncSetAttribute(attn_mma_kernel,
                         cudaFuncAttributeMaxDynamicSharedMemorySize,
                         (int)ATTN_SMEM);
    attn_mma_kernel<<<dim3(SEQ/ABM, BATCH*NHEAD), 256, ATTN_SMEM>>>(Q, K, V, A);

    // Output projection
    gemm_bf16_kernel<<<dim3(HID/128, TOK/128), 256>>>(A, o_w, nullptr, out, HID, HID);
}